// round 7
// baseline (speedup 1.0000x reference)
#include <cuda_runtime.h>
#include <cooperative_groups.h>
namespace cg = cooperative_groups;

#define NDIM 128
#define LD   132         // padded row stride (floats) -> conflict-free A reads
#define BLK  512         // 16 warps: 4/SMSP
#define CLUS 4

// shared-memory layout (float offsets)
#define OFF_W    0              // 128*132 = 16896
#define OFF_Z    16896          // 128*132 (full Z, global-row indexed)
#define OFF_A    33792          // 32*132 local rows (interleaved ownership)
#define OFF_X    38016          // 32*132
#define OFF_XI   42240          // 128
#define OFF_PROB 42368          // 128
#define OFF_DINV 42496          // 128
#define OFF_RS   42624          // 2 x 128 (parity double buffer)
#define OFF_RED  42880          // 4
#define SMEM_FLOATS 42896       // 171584 bytes

// ---------- packed f32x2 helpers ----------
__device__ __forceinline__ unsigned long long pack2(float v) {
    unsigned long long r;
    asm("mov.b64 %0, {%1, %1};" : "=l"(r) : "f"(v));
    return r;
}
__device__ __forceinline__ void fma2(unsigned long long& d, unsigned long long a, unsigned long long b) {
    asm("fma.rn.f32x2 %0, %1, %2, %0;" : "+l"(d) : "l"(a), "l"(b));
}
__device__ __forceinline__ float2 unpack2(unsigned long long v) {
    float2 r;
    asm("mov.b64 {%0, %1}, %2;" : "=f"(r.x), "=f"(r.y) : "l"(v));
    return r;
}
__device__ __forceinline__ float4 acc_f4(const unsigned long long a0,
                                         const unsigned long long a1, bool relu) {
    float2 lo = unpack2(a0), hi = unpack2(a1);
    float4 v = make_float4(lo.x, lo.y, hi.x, hi.y);
    if (relu) { v.x = fmaxf(v.x,0.f); v.y = fmaxf(v.y,0.f); v.z = fmaxf(v.z,0.f); v.w = fmaxf(v.w,0.f); }
    return v;
}

// ---------- 32(local rows) x 128 x Kb GEMM: thread = 2 rows x 4 cols ----------
// 512 threads. Warp = 4 row-pairs x 8 col-groups (32 contiguous cols):
// B 128B/warp/k (1 wavefront); A 4 distinct rows/load, conflict-free via LD=132.
__device__ __forceinline__ void gemm_acc(const float* __restrict__ As,
                                         const float* __restrict__ Bs,
                                         int tr, int tc, int Kb,
                                         unsigned long long acc[2][2])
{
    acc[0][0] = acc[0][1] = acc[1][0] = acc[1][1] = 0ull;

#pragma unroll 2
    for (int k = 0; k < Kb; k += 4) {
        const float4 a0 = *(const float4*)(As + tr * LD + k);
        const float4 a1 = *(const float4*)(As + (tr + 1) * LD + k);
        ulonglong2 b[4];
#pragma unroll
        for (int kk = 0; kk < 4; ++kk)
            b[kk] = *(const ulonglong2*)(Bs + (k + kk) * LD + tc);
#pragma unroll
        for (int kk = 0; kk < 4; ++kk) {
            const unsigned long long p0 = pack2(((const float*)&a0)[kk]);
            fma2(acc[0][0], p0, b[kk].x);
            fma2(acc[0][1], p0, b[kk].y);
            const unsigned long long p1 = pack2(((const float*)&a1)[kk]);
            fma2(acc[1][0], p1, b[kk].x);
            fma2(acc[1][1], p1, b[kk].y);
        }
    }
}

__global__ void __launch_bounds__(BLK, 1) __cluster_dims__(CLUS, 1, 1)
gcn_kernel(const float* __restrict__ xg, const float* __restrict__ Wg,
           float* __restrict__ outg)
{
    extern __shared__ float sm[];
    float* Ws   = sm + OFF_W;
    float* Z    = sm + OFF_Z;
    float* A    = sm + OFF_A;
    float* X    = sm + OFF_X;
    float* xi   = sm + OFF_XI;
    float* prob = sm + OFF_PROB;
    float* dinv = sm + OFF_DINV;
    float* red  = sm + OFF_RED;

    cg::cluster_group cl = cg::this_cluster();
    const int rank  = (int)cl.block_rank();
    const int tid   = threadIdx.x;
    const int batch = blockIdx.x / CLUS;

    // GEMM mapping: warp = 4 row-pairs x one 32-col block
    const int w = tid >> 5, l = tid & 31;
    const int tr = ((w >> 2) << 3) | ((l >> 3) << 1);   // row base (0..30, step 2)
    const int tc = ((w & 3) << 5) | ((l & 7) << 2);     // col base (0..124)

    float* peer[CLUS];
#pragma unroll
    for (int r = 0; r < CLUS; ++r) peer[r] = (float*)cl.map_shared_rank((void*)sm, r);

    const float* __restrict__ xb = xg + (size_t)batch * 16384;
    float* __restrict__ ob = outg + (size_t)batch * 16384;

    // ---- prologue ----
    for (int idx = tid; idx < 4096; idx += BLK) {           // W -> padded smem
        const int row = idx >> 5, c4 = idx & 31;
        *(float4*)(Ws + row * LD + (c4 << 2)) = ((const float4*)Wg)[idx];
    }
    for (int idx = tid; idx < 1024; idx += BLK) {           // local x rows -> Z temp
        const int jl = idx >> 5, c4 = idx & 31;
        const int g = (jl << 2) | rank;
        *(float4*)(Z + jl * LD + (c4 << 2)) =
            ((const float4*)(xb + (size_t)g * NDIM))[c4];
    }
    for (int idx = tid; idx < 1024; idx += BLK) {           // eye quarters
        const int jl = idx >> 5, c4 = idx & 31;
        const int g = (jl << 2) | rank;
        float4 e = make_float4(0.f, 0.f, 0.f, 0.f);
        const int d = g - (c4 << 2);
        if (d >= 0 && d < 4) ((float*)&e)[d] = 1.0f;
        *(float4*)(A + jl * LD + (c4 << 2)) = e;
        ((float4*)(ob + (size_t)g * NDIM))[c4] = e;
    }
    if (tid < NDIM) sm[OFF_RS + NDIM + tid] = 1.0f;         // rs parity buf for i=1
    __syncthreads();

    // X_local = relu(x_local @ W)
    {
        unsigned long long acc[2][2];
        gemm_acc(Z, Ws, tr, tc, NDIM, acc);
        *(float4*)(X + tr * LD + tc)       = acc_f4(acc[0][0], acc[0][1], true);
        *(float4*)(X + (tr + 1) * LD + tc) = acc_f4(acc[1][0], acc[1][1], true);
    }
    __syncthreads();

    // broadcast X row 1 (global row 1 => rank 1, jl 0)
    if (rank == 1 && tid < 32) {
        const float4 v = *(const float4*)(X + (tid << 2));
#pragma unroll
        for (int r = 0; r < CLUS; ++r)
            ((float4*)(peer[r] + OFF_XI))[tid] = v;
    }
    cl.sync();

    for (int i = 1; i < NDIM; ++i) {
        int Kb = (i + 4) & ~3;
        if (Kb > NDIM) Kb = NDIM;

        // ---- prob[g] = dot(X_local[jl], xi); scatter. 16 threads/row ----
        {
            const int jl = tid >> 4, p = tid & 15;
            const float* xrow = X + jl * LD;
            float s = 0.f;
#pragma unroll
            for (int q = 0; q < 2; ++q) {
                const int c4 = p + (q << 4);
                const float4 u = *(const float4*)(xrow + (c4 << 2));
                const float4 v = ((const float4*)xi)[c4];
                s += u.x * v.x + u.y * v.y + u.z * v.z + u.w * v.w;
            }
            s += __shfl_down_sync(0xffffffffu, s, 8);
            s += __shfl_down_sync(0xffffffffu, s, 4);
            s += __shfl_down_sync(0xffffffffu, s, 2);
            s += __shfl_down_sync(0xffffffffu, s, 1);
            if (p == 0) {
                const int g = (jl << 2) | rank;
#pragma unroll
                for (int r = 0; r < CLUS; ++r)
                    peer[r][OFF_PROB + g] = s;
            }
        }

        // ---- Z = X_local @ W; local always, remote only rows g < Kb ----
        if (i < NDIM - 1) {
            unsigned long long acc[2][2];
            gemm_acc(X, Ws, tr, tc, NDIM, acc);
#pragma unroll
            for (int r = 0; r < 2; ++r) {
                const float4 v = acc_f4(acc[r][0], acc[r][1], false);
                const int g = ((tr + r) << 2) | rank;
                *(float4*)(Z + g * LD + tc) = v;
                if (g < Kb) {
#pragma unroll
                    for (int q = 0; q < CLUS; ++q)
                        if (q != rank)
                            *(float4*)(peer[q] + OFF_Z + g * LD + tc) = v;
                }
            }
        }
        cl.sync();   // prob + Z visible everywhere

        // ---- partial reduce of sum_{j<i} prob[j] (warps 0-3) ----
        if (tid < NDIM) {
            float ps = (tid < i) ? prob[tid] : 0.f;
            ps += __shfl_down_sync(0xffffffffu, ps, 16);
            ps += __shfl_down_sync(0xffffffffu, ps, 8);
            ps += __shfl_down_sync(0xffffffffu, ps, 4);
            ps += __shfl_down_sync(0xffffffffu, ps, 2);
            ps += __shfl_down_sync(0xffffffffu, ps, 1);
            if (l == 0) red[w] = ps;
        }
        // ---- splice col i into local A rows + output ----
        if (tid < 32) {
            const int jl = tid, g = (jl << 2) | rank;
            if (g < i) {
                const float pv = prob[g];
                A[jl * LD + i] = pv;
                ob[(size_t)g * NDIM + i] = pv;
            }
        }
        // ---- splice row i (owner) + output ----
        if (rank == (i & 3) && tid >= 64 && (tid - 64) < i) {
            const int il = i >> 2, j = tid - 64;
            const float pv = prob[j];
            A[il * LD + j] = pv;
            ob[(size_t)i * NDIM + j] = pv;
        }
        if (i == NDIM - 1) break;
        __syncthreads();

        // ---- full dinv computed locally by every CTA (no exchange) ----
        if (tid < NDIM) {
            const float sp = red[0] + red[1] + red[2] + red[3];
            float dg = sm[OFF_RS + ((i & 1) << 7) + tid];
            if (tid < i)       dg += prob[tid];
            else if (tid == i) dg += sp;
            float rv = rsqrtf(dg);
            rv = rv * (1.5f - 0.5f * dg * rv * rv);   // Newton refine
            dinv[tid] = rv;
        }
        __syncthreads();

        // ---- normalize local A rows; accumulate rs_next; scatter rs ----
        {
            const int jl = tid >> 4, p = tid & 15;
            const int g = (jl << 2) | rank;
            const float dr = dinv[g];
            float* arow = A + jl * LD;
            float s = 0.f;
#pragma unroll
            for (int q = 0; q < 2; ++q) {
                const int c4 = p + (q << 4);
                const float4 dc = ((const float4*)dinv)[c4];
                float4 v = *(float4*)(arow + (c4 << 2));
                v.x *= dr * dc.x; v.y *= dr * dc.y;
                v.z *= dr * dc.z; v.w *= dr * dc.w;
                *(float4*)(arow + (c4 << 2)) = v;
                s += v.x + v.y + v.z + v.w;
            }
            s += __shfl_down_sync(0xffffffffu, s, 8);
            s += __shfl_down_sync(0xffffffffu, s, 4);
            s += __shfl_down_sync(0xffffffffu, s, 2);
            s += __shfl_down_sync(0xffffffffu, s, 1);
            if (p == 0) {
                const int dst = OFF_RS + (((i & 1) ^ 1) << 7) + g;
#pragma unroll
                for (int r = 0; r < CLUS; ++r)
                    peer[r][dst] = s;
            }
        }
        __syncthreads();

        // ---- X_local = relu(A_local @ Z) for rows g<Kb, else relu(Z[g]) ----
        {
            const int m = Kb >> 2;    // active local rows per CTA
            unsigned long long acc[2][2];
            if (tr < m) gemm_acc(A, Z, tr, tc, Kb, acc);
#pragma unroll
            for (int r = 0; r < 2; ++r) {
                const int jl = tr + r, g = (jl << 2) | rank;
                float4 v;
                if (jl < m) {
                    v = acc_f4(acc[r][0], acc[r][1], true);
                } else {
                    v = *(const float4*)(Z + g * LD + tc);
                    v.x = fmaxf(v.x, 0.f); v.y = fmaxf(v.y, 0.f);
                    v.z = fmaxf(v.z, 0.f); v.w = fmaxf(v.w, 0.f);
                }
                *(float4*)(X + jl * LD + tc) = v;
            }
        }
        __syncthreads();

        // ---- broadcast X row (i+1) from its owner ----
        {
            const int ni = i + 1;
            if (rank == (ni & 3) && tid < 32) {
                const float4 v = *(const float4*)(X + (ni >> 2) * LD + (tid << 2));
#pragma unroll
                for (int r = 0; r < CLUS; ++r)
                    ((float4*)(peer[r] + OFF_XI))[tid] = v;
            }
        }
        cl.sync();   // rs + xi + X visible; Z free for next iter
    }
}

extern "C" void kernel_launch(void* const* d_in, const int* in_sizes, int n_in,
                              void* d_out, int out_size)
{
    const float* x = (const float*)d_in[0];
    const float* W = (const float*)d_in[1];
    if (n_in >= 2 && in_sizes[0] == 16384 && in_sizes[1] != 16384) {
        const float* t = x; x = W; W = t;
    }
    float* out = (float*)d_out;

    const size_t smem_bytes = (size_t)SMEM_FLOATS * sizeof(float);  // 171584
    cudaFuncSetAttribute(gcn_kernel, cudaFuncAttributeMaxDynamicSharedMemorySize,
                         (int)smem_bytes);
    gcn_kernel<<<32 * CLUS, BLK, smem_bytes>>>(x, W, out);
}

// round 9
// speedup vs baseline: 1.2885x; 1.2885x over previous
#include <cuda_runtime.h>
#include <cooperative_groups.h>
namespace cg = cooperative_groups;

#define NDIM 128
#define BLK  256         // 8 warps
#define CLUS 4

// shared-memory layout (float offsets)
#define OFF_W    0              // 16384
#define OFF_Z    16384          // 16384 (full Z, global-row indexed)
#define OFF_A    32768          // 32x128 local rows (interleaved ownership)
#define OFF_X    36864          // 32x128 local rows
#define OFF_XI   40960          // 128
#define OFF_PROB 41088          // 128
#define OFF_DINV 41216          // 128
#define OFF_RS   41344          // 2 x 128 (parity double buffer)
#define OFF_BAR  41600          // 2 x u64 mbarriers (8B aligned)
#define SMEM_FLOATS 41608       // 166432 bytes

// ---------- packed f32x2 helpers ----------
__device__ __forceinline__ unsigned long long pack2(float v) {
    unsigned long long r;
    asm("mov.b64 %0, {%1, %1};" : "=l"(r) : "f"(v));
    return r;
}
__device__ __forceinline__ void fma2(unsigned long long& d, unsigned long long a, unsigned long long b) {
    asm("fma.rn.f32x2 %0, %1, %2, %0;" : "+l"(d) : "l"(a), "l"(b));
}
__device__ __forceinline__ float2 unpack2(unsigned long long v) {
    float2 r;
    asm("mov.b64 {%0, %1}, %2;" : "=f"(r.x), "=f"(r.y) : "l"(v));
    return r;
}
__device__ __forceinline__ float4 acc_f4(const unsigned long long a0,
                                         const unsigned long long a1, bool relu) {
    float2 lo = unpack2(a0), hi = unpack2(a1);
    float4 v = make_float4(lo.x, lo.y, hi.x, hi.y);
    if (relu) { v.x = fmaxf(v.x,0.f); v.y = fmaxf(v.y,0.f); v.z = fmaxf(v.z,0.f); v.w = fmaxf(v.w,0.f); }
    return v;
}

__device__ __forceinline__ unsigned smem_u32(const void* p) {
    unsigned a;
    asm("{ .reg .u64 t; cvta.to.shared.u64 t, %1; cvt.u32.u64 %0, t; }"
        : "=r"(a) : "l"(p));
    return a;
}

// mbarrier-based cluster barrier: syncthreads, 4 parallel remote arrives, wait.
__device__ __forceinline__ void cluster_bar(unsigned bar, int tid, unsigned parity) {
    __syncthreads();
    if (tid < CLUS) {
        unsigned remote;
        asm volatile("mapa.shared::cluster.u32 %0, %1, %2;"
                     : "=r"(remote) : "r"(bar), "r"(tid));
        asm volatile("mbarrier.arrive.release.cluster.shared::cluster.b64 _, [%0];"
                     :: "r"(remote) : "memory");
    }
    asm volatile("{\n\t"
        ".reg .pred P;\n\t"
        "WAITLOOP%=:\n\t"
        "mbarrier.try_wait.parity.acquire.cluster.shared::cta.b64 P, [%0], %1, 0x989680;\n\t"
        "@!P bra WAITLOOP%=;\n\t"
        "}" :: "r"(bar), "r"(parity) : "memory");
}

// ---------- 32(local rows) x 128 x Kb GEMM: thread = 4 rows x 4 cols ----------
// 256 threads. Warp = 2 row-groups x 16 col-groups over one 64-col half:
// B reads dedup to 256B/warp/k.
__device__ __forceinline__ void gemm_acc(const float* __restrict__ As,
                                         const float* __restrict__ Bs,
                                         int tr, int tc, int Kb,
                                         unsigned long long acc[4][2])
{
#pragma unroll
    for (int r = 0; r < 4; ++r) { acc[r][0] = 0ull; acc[r][1] = 0ull; }

#pragma unroll 4
    for (int k = 0; k < Kb; k += 4) {
        float4 a[4];
#pragma unroll
        for (int r = 0; r < 4; ++r)
            a[r] = *(const float4*)(As + (tr + r) * NDIM + k);
        ulonglong2 b[4];
#pragma unroll
        for (int kk = 0; kk < 4; ++kk)
            b[kk] = *(const ulonglong2*)(Bs + (k + kk) * NDIM + tc);
#pragma unroll
        for (int kk = 0; kk < 4; ++kk) {
#pragma unroll
            for (int r = 0; r < 4; ++r) {
                const unsigned long long p = pack2(((const float*)&a[r])[kk]);
                fma2(acc[r][0], p, b[kk].x);
                fma2(acc[r][1], p, b[kk].y);
            }
        }
    }
}

__global__ void __launch_bounds__(BLK, 1) __cluster_dims__(CLUS, 1, 1)
gcn_kernel(const float* __restrict__ xg, const float* __restrict__ Wg,
           float* __restrict__ outg)
{
    extern __shared__ float sm[];
    float* Ws   = sm + OFF_W;
    float* Z    = sm + OFF_Z;
    float* A    = sm + OFF_A;
    float* X    = sm + OFF_X;
    float* xi   = sm + OFF_XI;
    float* prob = sm + OFF_PROB;
    float* dinv = sm + OFF_DINV;

    cg::cluster_group cl = cg::this_cluster();
    const int rank  = (int)cl.block_rank();
    const int tid   = threadIdx.x;
    const int batch = blockIdx.x / CLUS;

    const unsigned bar0 = smem_u32(sm + OFF_BAR);
    const unsigned bar1 = bar0 + 8;
    unsigned ph0 = 0, ph1 = 0;

    // interleaved ownership: local row jl <-> global row g = 4*jl + rank
    const int w = tid >> 5, l = tid & 31;
    const int rg = ((w >> 1) << 1) | (l >> 4);         // 0..7
    const int cgp = (l & 15) | ((w & 1) << 4);         // 0..31
    const int tr = rg << 2;                            // 0..28
    const int tc = cgp << 2;                           // 0..124
    const unsigned gmask8 = 0xFFu << (l & 24);         // 8-lane group mask (same jl)

    float* peer[CLUS];
#pragma unroll
    for (int r = 0; r < CLUS; ++r) peer[r] = (float*)cl.map_shared_rank((void*)sm, r);

    const float* __restrict__ xb = xg + (size_t)batch * 16384;
    float* __restrict__ ob = outg + (size_t)batch * 16384;

    // ---- prologue ----
    if (tid == 0) {
        asm volatile("mbarrier.init.shared.b64 [%0], %1;" :: "r"(bar0), "r"(CLUS) : "memory");
        asm volatile("mbarrier.init.shared.b64 [%0], %1;" :: "r"(bar1), "r"(CLUS) : "memory");
    }
    for (int idx = tid; idx < 4096; idx += BLK)
        ((float4*)Ws)[idx] = ((const float4*)Wg)[idx];
    for (int idx = tid; idx < 1024; idx += BLK) {           // local x rows -> Z temp
        const int jl = idx >> 5, c4 = idx & 31;
        const int g = (jl << 2) | rank;
        ((float4*)(Z + jl * NDIM))[c4] = ((const float4*)(xb + (size_t)g * NDIM))[c4];
    }
    for (int idx = tid; idx < 1024; idx += BLK) {           // eye quarters
        const int jl = idx >> 5, c4 = idx & 31;
        const int g = (jl << 2) | rank;
        float4 e = make_float4(0.f, 0.f, 0.f, 0.f);
        const int d = g - (c4 << 2);
        if (d >= 0 && d < 4) ((float*)&e)[d] = 1.0f;
        ((float4*)(A + jl * NDIM))[c4] = e;
        ((float4*)(ob + (size_t)g * NDIM))[c4] = e;
    }
    if (tid < NDIM) sm[OFF_RS + NDIM + tid] = 1.0f;         // rs parity buf for i=1
    __syncthreads();

    // X_local = relu(x_local @ W)
    {
        unsigned long long acc[4][2];
        gemm_acc(Z, Ws, tr, tc, NDIM, acc);
#pragma unroll
        for (int r = 0; r < 4; ++r)
            *(float4*)(X + (tr + r) * NDIM + tc) = acc_f4(acc[r][0], acc[r][1], true);
    }
    __syncthreads();

    // broadcast X row 1 (global row 1 => rank 1, jl 0)
    if (rank == 1 && tid < 32) {
        const float4 v = ((const float4*)X)[tid];
#pragma unroll
        for (int r = 0; r < CLUS; ++r)
            ((float4*)(peer[r] + OFF_XI))[tid] = v;
    }
    cl.sync();   // covers prologue + mbarrier init + xi

    for (int i = 1; i < NDIM; ++i) {
        int Kb = (i + 4) & ~3;
        if (Kb > NDIM) Kb = NDIM;

        // ---- prob[g] = dot(X_local[jl], xi), only rows g < i; scatter ----
        // NOTE: g is uniform within each 8-lane group -> use gmask8 for shfl.
        {
            const int jl = tid >> 3, p = tid & 7;
            const int g = (jl << 2) | rank;
            if (g < i) {
                const float4* xj = (const float4*)(X + jl * NDIM) + (p << 2);
                const float4* xv = (const float4*)xi + (p << 2);
                float s = 0.f;
#pragma unroll
                for (int q = 0; q < 4; ++q) {
                    const float4 u = xj[q], v = xv[q];
                    s += u.x * v.x + u.y * v.y + u.z * v.z + u.w * v.w;
                }
                s += __shfl_down_sync(gmask8, s, 4);
                s += __shfl_down_sync(gmask8, s, 2);
                s += __shfl_down_sync(gmask8, s, 1);
                if (p == 0) {
#pragma unroll
                    for (int r = 0; r < CLUS; ++r)
                        peer[r][OFF_PROB + g] = s;
                }
            }
        }

        // ---- Z = X_local @ W; local always, remote only rows g < Kb ----
        if (i < NDIM - 1) {
            unsigned long long acc[4][2];
            gemm_acc(X, Ws, tr, tc, NDIM, acc);
#pragma unroll
            for (int r = 0; r < 4; ++r) {
                const float4 v = acc_f4(acc[r][0], acc[r][1], false);
                const int g = ((tr + r) << 2) | rank;
                *(float4*)(Z + g * NDIM + tc) = v;
                if (g < Kb) {
#pragma unroll
                    for (int q = 0; q < CLUS; ++q)
                        if (q != rank)
                            *(float4*)(peer[q] + OFF_Z + g * NDIM + tc) = v;
                }
            }
        }
        cluster_bar(bar0, tid, ph0); ph0 ^= 1;   // prob + Z visible everywhere

        if (i == NDIM - 1) {
            // output-only splice for the final step
            if (tid < 32) {
                const int g = (tid << 2) | rank;
                if (g < i) ob[(size_t)g * NDIM + i] = prob[g];
            }
            if (rank == (i & 3))
                for (int j = tid; j < i; j += BLK)
                    ob[(size_t)i * NDIM + j] = prob[j];
            break;
        }

        // ---- P1: per-warp butterfly sp (warps 0-3, full warps); dinv ----
        if (tid < NDIM) {
            const int ll = tid & 31;
            float sp = ((ll      < i) ? prob[ll]      : 0.f)
                     + ((ll + 32 < i) ? prob[ll + 32] : 0.f)
                     + ((ll + 64 < i) ? prob[ll + 64] : 0.f)
                     + ((ll + 96 < i) ? prob[ll + 96] : 0.f);
            sp += __shfl_xor_sync(0xffffffffu, sp, 16);
            sp += __shfl_xor_sync(0xffffffffu, sp, 8);
            sp += __shfl_xor_sync(0xffffffffu, sp, 4);
            sp += __shfl_xor_sync(0xffffffffu, sp, 2);
            sp += __shfl_xor_sync(0xffffffffu, sp, 1);
            float dg = sm[OFF_RS + ((i & 1) << 7) + tid];
            if (tid < i)       dg += prob[tid];
            else if (tid == i) dg += sp;
            float rv = rsqrtf(dg);
            rv = rv * (1.5f - 0.5f * dg * rv * rv);   // Newton refine
            dinv[tid] = rv;
        }
        __syncthreads();

        // ---- P2: fused splice + normalize + rowsum, rows g <= i only ----
        // NOTE: g uniform within 8-lane group -> gmask8 for the rowsum shfl.
        {
            const int jl = tid >> 3, p = tid & 7;
            const int g = (jl << 2) | rank;
            const int dstRS = OFF_RS + (((i & 1) ^ 1) << 7) + g;
            if (g <= i) {
                const float dr = dinv[g];
                const bool rowi = (g == i);
                float* arow = A + jl * NDIM;
                float s = 0.f;
#pragma unroll
                for (int q = 0; q < 4; ++q) {
                    const int c4 = p + (q << 3);
                    const int c = c4 << 2;
                    float4 v = ((float4*)arow)[c4];
                    if (rowi) {
                        if (c + 0 < i) { v.x = prob[c+0]; ob[(size_t)i*NDIM + c+0] = v.x; }
                        if (c + 1 < i) { v.y = prob[c+1]; ob[(size_t)i*NDIM + c+1] = v.y; }
                        if (c + 2 < i) { v.z = prob[c+2]; ob[(size_t)i*NDIM + c+2] = v.z; }
                        if (c + 3 < i) { v.w = prob[c+3]; ob[(size_t)i*NDIM + c+3] = v.w; }
                    } else if ((i >> 2) == c4) {
                        const float pv = prob[g];
                        ((float*)&v)[i & 3] = pv;
                        ob[(size_t)g * NDIM + i] = pv;
                    }
                    const float4 dc = ((const float4*)dinv)[c4];
                    v.x *= dr * dc.x; v.y *= dr * dc.y;
                    v.z *= dr * dc.z; v.w *= dr * dc.w;
                    ((float4*)arow)[c4] = v;
                    s += v.x + v.y + v.z + v.w;
                }
                s += __shfl_down_sync(gmask8, s, 4);
                s += __shfl_down_sync(gmask8, s, 2);
                s += __shfl_down_sync(gmask8, s, 1);
                if (p == 0) {
#pragma unroll
                    for (int r = 0; r < CLUS; ++r)
                        peer[r][dstRS] = s;
                }
            } else if (p == 0) {
                // untouched rows stay e_g: rowsum of normalized row = 1
#pragma unroll
                for (int r = 0; r < CLUS; ++r)
                    peer[r][dstRS] = 1.0f;
            }
        }
        __syncthreads();

        // ---- X_local = relu(A_local @ Z) for rows g<Kb, else relu(Z[g]) ----
        {
            const int m = Kb >> 2;    // active local rows per CTA
            unsigned long long acc[4][2];
            if (tr < m) gemm_acc(A, Z, tr, tc, Kb, acc);
#pragma unroll
            for (int r = 0; r < 4; ++r) {
                const int jl = tr + r, g = (jl << 2) | rank;
                float4 v;
                if (jl < m) {
                    v = acc_f4(acc[r][0], acc[r][1], true);
                } else {
                    v = *(const float4*)(Z + g * NDIM + tc);
                    v.x = fmaxf(v.x, 0.f); v.y = fmaxf(v.y, 0.f);
                    v.z = fmaxf(v.z, 0.f); v.w = fmaxf(v.w, 0.f);
                }
                *(float4*)(X + jl * NDIM + tc) = v;
            }
        }
        __syncthreads();

        // ---- broadcast X row (i+1) from its owner ----
        {
            const int ni = i + 1;
            if (rank == (ni & 3) && tid < 32) {
                const float4 v = ((const float4*)(X + (ni >> 2) * NDIM))[tid];
#pragma unroll
                for (int r = 0; r < CLUS; ++r)
                    ((float4*)(peer[r] + OFF_XI))[tid] = v;
            }
        }
        cluster_bar(bar1, tid, ph1); ph1 ^= 1;   // rs + xi visible; Z reusable
    }
}

extern "C" void kernel_launch(void* const* d_in, const int* in_sizes, int n_in,
                              void* d_out, int out_size)
{
    const float* x = (const float*)d_in[0];
    const float* W = (const float*)d_in[1];
    if (n_in >= 2 && in_sizes[0] == 16384 && in_sizes[1] != 16384) {
        const float* t = x; x = W; W = t;
    }
    float* out = (float*)d_out;

    const size_t smem_bytes = (size_t)SMEM_FLOATS * sizeof(float);  // 166432
    cudaFuncSetAttribute(gcn_kernel, cudaFuncAttributeMaxDynamicSharedMemorySize,
                         (int)smem_bytes);
    gcn_kernel<<<32 * CLUS, BLK, smem_bytes>>>(x, W, out);
}

// round 10
// speedup vs baseline: 1.2888x; 1.0003x over previous
#include <cuda_runtime.h>
#include <cooperative_groups.h>
namespace cg = cooperative_groups;

#define NDIM 128
#define BLK  256         // 8 warps
#define CLUS 4

// shared-memory layout (float offsets)
#define OFF_W    0              // 16384
#define OFF_Z    16384          // 16384 (full Z, global-row indexed)
#define OFF_A    32768          // 32x128 local rows (interleaved ownership)
#define OFF_X    36864          // 32x128 local rows
#define OFF_XI   40960          // 128
#define OFF_PROB 41088          // 128
#define OFF_DINV 41216          // 128
#define OFF_RS   41344          // 2 x 128 (parity double buffer)
#define OFF_BAR  41600          // 2 x u64 mbarriers (8B aligned)
#define SMEM_FLOATS 41608       // 166432 bytes

// ---------- packed f32x2 helpers ----------
__device__ __forceinline__ unsigned long long pack2(float v) {
    unsigned long long r;
    asm("mov.b64 %0, {%1, %1};" : "=l"(r) : "f"(v));
    return r;
}
__device__ __forceinline__ void fma2(unsigned long long& d, unsigned long long a, unsigned long long b) {
    asm("fma.rn.f32x2 %0, %1, %2, %0;" : "+l"(d) : "l"(a), "l"(b));
}
__device__ __forceinline__ float2 unpack2(unsigned long long v) {
    float2 r;
    asm("mov.b64 {%0, %1}, %2;" : "=f"(r.x), "=f"(r.y) : "l"(v));
    return r;
}
__device__ __forceinline__ float4 acc_f4(const unsigned long long a0,
                                         const unsigned long long a1, bool relu) {
    float2 lo = unpack2(a0), hi = unpack2(a1);
    float4 v = make_float4(lo.x, lo.y, hi.x, hi.y);
    if (relu) { v.x = fmaxf(v.x,0.f); v.y = fmaxf(v.y,0.f); v.z = fmaxf(v.z,0.f); v.w = fmaxf(v.w,0.f); }
    return v;
}

__device__ __forceinline__ unsigned smem_u32(const void* p) {
    unsigned a;
    asm("{ .reg .u64 t; cvta.to.shared.u64 t, %1; cvt.u32.u64 %0, t; }"
        : "=r"(a) : "l"(p));
    return a;
}

// mbarrier-based cluster barrier: syncthreads, 4 parallel remote arrives, wait.
__device__ __forceinline__ void cluster_bar(unsigned bar, int tid, unsigned parity) {
    __syncthreads();
    if (tid < CLUS) {
        unsigned remote;
        asm volatile("mapa.shared::cluster.u32 %0, %1, %2;"
                     : "=r"(remote) : "r"(bar), "r"(tid));
        asm volatile("mbarrier.arrive.release.cluster.shared::cluster.b64 _, [%0];"
                     :: "r"(remote) : "memory");
    }
    asm volatile("{\n\t"
        ".reg .pred P;\n\t"
        "WAITLOOP%=:\n\t"
        "mbarrier.try_wait.parity.acquire.cluster.shared::cta.b64 P, [%0], %1, 0x989680;\n\t"
        "@!P bra WAITLOOP%=;\n\t"
        "}" :: "r"(bar), "r"(parity) : "memory");
}

// ---------- 32(local rows) x 128 x Kb GEMM: thread = 4 rows x 4 cols ----------
// 256 threads. Warp = 2 row-groups x 16 col-groups over one 64-col half:
// B reads dedup to 256B/warp/k.
__device__ __forceinline__ void gemm_acc(const float* __restrict__ As,
                                         const float* __restrict__ Bs,
                                         int tr, int tc, int Kb,
                                         unsigned long long acc[4][2])
{
#pragma unroll
    for (int r = 0; r < 4; ++r) { acc[r][0] = 0ull; acc[r][1] = 0ull; }

#pragma unroll 4
    for (int k = 0; k < Kb; k += 4) {
        float4 a[4];
#pragma unroll
        for (int r = 0; r < 4; ++r)
            a[r] = *(const float4*)(As + (tr + r) * NDIM + k);
        ulonglong2 b[4];
#pragma unroll
        for (int kk = 0; kk < 4; ++kk)
            b[kk] = *(const ulonglong2*)(Bs + (k + kk) * NDIM + tc);
#pragma unroll
        for (int kk = 0; kk < 4; ++kk) {
#pragma unroll
            for (int r = 0; r < 4; ++r) {
                const unsigned long long p = pack2(((const float*)&a[r])[kk]);
                fma2(acc[r][0], p, b[kk].x);
                fma2(acc[r][1], p, b[kk].y);
            }
        }
    }
}

__global__ void __launch_bounds__(BLK, 1) __cluster_dims__(CLUS, 1, 1)
gcn_kernel(const float* __restrict__ xg, const float* __restrict__ Wg,
           float* __restrict__ outg)
{
    extern __shared__ float sm[];
    float* Ws   = sm + OFF_W;
    float* Z    = sm + OFF_Z;
    float* A    = sm + OFF_A;
    float* X    = sm + OFF_X;
    float* xi   = sm + OFF_XI;
    float* prob = sm + OFF_PROB;
    float* dinv = sm + OFF_DINV;

    cg::cluster_group cl = cg::this_cluster();
    const int rank  = (int)cl.block_rank();
    const int tid   = threadIdx.x;
    const int batch = blockIdx.x / CLUS;

    const unsigned bar0 = smem_u32(sm + OFF_BAR);
    const unsigned bar1 = bar0 + 8;
    unsigned ph0 = 0, ph1 = 0;

    // interleaved ownership: local row jl <-> global row g = 4*jl + rank
    const int w = tid >> 5, l = tid & 31;
    const int rg = ((w >> 1) << 1) | (l >> 4);         // 0..7
    const int cgp = (l & 15) | ((w & 1) << 4);         // 0..31
    const int tr = rg << 2;                            // 0..28
    const int tc = cgp << 2;                           // 0..124
    const unsigned gmask8 = 0xFFu << (l & 24);         // 8-lane group mask (same jl)

    float* peer[CLUS];
#pragma unroll
    for (int r = 0; r < CLUS; ++r) peer[r] = (float*)cl.map_shared_rank((void*)sm, r);

    const float* __restrict__ xb = xg + (size_t)batch * 16384;
    float* __restrict__ ob = outg + (size_t)batch * 16384;

    // ---- prologue ----
    if (tid == 0) {
        asm volatile("mbarrier.init.shared.b64 [%0], %1;" :: "r"(bar0), "r"(CLUS) : "memory");
        asm volatile("mbarrier.init.shared.b64 [%0], %1;" :: "r"(bar1), "r"(CLUS) : "memory");
    }
    for (int idx = tid; idx < 4096; idx += BLK)
        ((float4*)Ws)[idx] = ((const float4*)Wg)[idx];
    for (int idx = tid; idx < 1024; idx += BLK) {           // local x rows -> Z temp
        const int jl = idx >> 5, c4 = idx & 31;
        const int g = (jl << 2) | rank;
        ((float4*)(Z + jl * NDIM))[c4] = ((const float4*)(xb + (size_t)g * NDIM))[c4];
    }
    for (int idx = tid; idx < 1024; idx += BLK) {           // eye quarters
        const int jl = idx >> 5, c4 = idx & 31;
        const int g = (jl << 2) | rank;
        float4 e = make_float4(0.f, 0.f, 0.f, 0.f);
        const int d = g - (c4 << 2);
        if (d >= 0 && d < 4) ((float*)&e)[d] = 1.0f;
        ((float4*)(A + jl * NDIM))[c4] = e;
        ((float4*)(ob + (size_t)g * NDIM))[c4] = e;
    }
    if (tid < NDIM) sm[OFF_RS + NDIM + tid] = 1.0f;         // rs parity buf for i=1
    __syncthreads();

    // X_local = relu(x_local @ W)
    {
        unsigned long long acc[4][2];
        gemm_acc(Z, Ws, tr, tc, NDIM, acc);
#pragma unroll
        for (int r = 0; r < 4; ++r)
            *(float4*)(X + (tr + r) * NDIM + tc) = acc_f4(acc[r][0], acc[r][1], true);
    }
    __syncthreads();

    // broadcast X row 1 (global row 1 => rank 1, jl 0)
    if (rank == 1 && tid < 32) {
        const float4 v = ((const float4*)X)[tid];
#pragma unroll
        for (int r = 0; r < CLUS; ++r)
            ((float4*)(peer[r] + OFF_XI))[tid] = v;
    }
    cl.sync();   // covers prologue + mbarrier init + xi

    for (int i = 1; i < NDIM; ++i) {
        int Kb = (i + 4) & ~3;
        if (Kb > NDIM) Kb = NDIM;

        // ---- prob[g] = dot(X_local[jl], xi), only rows g < i; scatter ----
        // NOTE: g is uniform within each 8-lane group -> use gmask8 for shfl.
        {
            const int jl = tid >> 3, p = tid & 7;
            const int g = (jl << 2) | rank;
            if (g < i) {
                const float4* xj = (const float4*)(X + jl * NDIM) + (p << 2);
                const float4* xv = (const float4*)xi + (p << 2);
                float s = 0.f;
#pragma unroll
                for (int q = 0; q < 4; ++q) {
                    const float4 u = xj[q], v = xv[q];
                    s += u.x * v.x + u.y * v.y + u.z * v.z + u.w * v.w;
                }
                s += __shfl_down_sync(gmask8, s, 4);
                s += __shfl_down_sync(gmask8, s, 2);
                s += __shfl_down_sync(gmask8, s, 1);
                if (p == 0) {
#pragma unroll
                    for (int r = 0; r < CLUS; ++r)
                        peer[r][OFF_PROB + g] = s;
                }
            }
        }

        // ---- Z = X_local @ W; local always, remote only rows g < Kb ----
        if (i < NDIM - 1) {
            unsigned long long acc[4][2];
            gemm_acc(X, Ws, tr, tc, NDIM, acc);
#pragma unroll
            for (int r = 0; r < 4; ++r) {
                const float4 v = acc_f4(acc[r][0], acc[r][1], false);
                const int g = ((tr + r) << 2) | rank;
                *(float4*)(Z + g * NDIM + tc) = v;
                if (g < Kb) {
#pragma unroll
                    for (int q = 0; q < CLUS; ++q)
                        if (q != rank)
                            *(float4*)(peer[q] + OFF_Z + g * NDIM + tc) = v;
                }
            }
        }
        cluster_bar(bar0, tid, ph0); ph0 ^= 1;   // prob + Z visible everywhere

        if (i == NDIM - 1) {
            // output-only splice for the final step
            if (tid < 32) {
                const int g = (tid << 2) | rank;
                if (g < i) ob[(size_t)g * NDIM + i] = prob[g];
            }
            if (rank == (i & 3))
                for (int j = tid; j < i; j += BLK)
                    ob[(size_t)i * NDIM + j] = prob[j];
            break;
        }

        // ---- P1: per-warp butterfly sp (warps 0-3, full warps); dinv ----
        if (tid < NDIM) {
            const int ll = tid & 31;
            float sp = ((ll      < i) ? prob[ll]      : 0.f)
                     + ((ll + 32 < i) ? prob[ll + 32] : 0.f)
                     + ((ll + 64 < i) ? prob[ll + 64] : 0.f)
                     + ((ll + 96 < i) ? prob[ll + 96] : 0.f);
            sp += __shfl_xor_sync(0xffffffffu, sp, 16);
            sp += __shfl_xor_sync(0xffffffffu, sp, 8);
            sp += __shfl_xor_sync(0xffffffffu, sp, 4);
            sp += __shfl_xor_sync(0xffffffffu, sp, 2);
            sp += __shfl_xor_sync(0xffffffffu, sp, 1);
            float dg = sm[OFF_RS + ((i & 1) << 7) + tid];
            if (tid < i)       dg += prob[tid];
            else if (tid == i) dg += sp;
            float rv = rsqrtf(dg);
            rv = rv * (1.5f - 0.5f * dg * rv * rv);   // Newton refine
            dinv[tid] = rv;
        }
        __syncthreads();

        // ---- P2: fused splice + normalize + rowsum, rows g <= i only ----
        // NOTE: g uniform within 8-lane group -> gmask8 for the rowsum shfl.
        {
            const int jl = tid >> 3, p = tid & 7;
            const int g = (jl << 2) | rank;
            const int dstRS = OFF_RS + (((i & 1) ^ 1) << 7) + g;
            if (g <= i) {
                const float dr = dinv[g];
                const bool rowi = (g == i);
                float* arow = A + jl * NDIM;
                float s = 0.f;
#pragma unroll
                for (int q = 0; q < 4; ++q) {
                    const int c4 = p + (q << 3);
                    const int c = c4 << 2;
                    float4 v = ((float4*)arow)[c4];
                    if (rowi) {
                        if (c + 0 < i) { v.x = prob[c+0]; ob[(size_t)i*NDIM + c+0] = v.x; }
                        if (c + 1 < i) { v.y = prob[c+1]; ob[(size_t)i*NDIM + c+1] = v.y; }
                        if (c + 2 < i) { v.z = prob[c+2]; ob[(size_t)i*NDIM + c+2] = v.z; }
                        if (c + 3 < i) { v.w = prob[c+3]; ob[(size_t)i*NDIM + c+3] = v.w; }
                    } else if ((i >> 2) == c4) {
                        const float pv = prob[g];
                        ((float*)&v)[i & 3] = pv;
                        ob[(size_t)g * NDIM + i] = pv;
                    }
                    const float4 dc = ((const float4*)dinv)[c4];
                    v.x *= dr * dc.x; v.y *= dr * dc.y;
                    v.z *= dr * dc.z; v.w *= dr * dc.w;
                    ((float4*)arow)[c4] = v;
                    s += v.x + v.y + v.z + v.w;
                }
                s += __shfl_down_sync(gmask8, s, 4);
                s += __shfl_down_sync(gmask8, s, 2);
                s += __shfl_down_sync(gmask8, s, 1);
                if (p == 0) {
#pragma unroll
                    for (int r = 0; r < CLUS; ++r)
                        peer[r][dstRS] = s;
                }
            } else if (p == 0) {
                // untouched rows stay e_g: rowsum of normalized row = 1
#pragma unroll
                for (int r = 0; r < CLUS; ++r)
                    peer[r][dstRS] = 1.0f;
            }
        }
        __syncthreads();

        // ---- X_local = relu(A_local @ Z) for rows g<Kb, else relu(Z[g]) ----
        {
            const int m = Kb >> 2;    // active local rows per CTA
            unsigned long long acc[4][2];
            if (tr < m) gemm_acc(A, Z, tr, tc, Kb, acc);
#pragma unroll
            for (int r = 0; r < 4; ++r) {
                const int jl = tr + r, g = (jl << 2) | rank;
                float4 v;
                if (jl < m) {
                    v = acc_f4(acc[r][0], acc[r][1], true);
                } else {
                    v = *(const float4*)(Z + g * NDIM + tc);
                    v.x = fmaxf(v.x, 0.f); v.y = fmaxf(v.y, 0.f);
                    v.z = fmaxf(v.z, 0.f); v.w = fmaxf(v.w, 0.f);
                }
                *(float4*)(X + jl * NDIM + tc) = v;
            }
        }
        __syncthreads();

        // ---- broadcast X row (i+1) from its owner ----
        {
            const int ni = i + 1;
            if (rank == (ni & 3) && tid < 32) {
                const float4 v = ((const float4*)(X + (ni >> 2) * NDIM))[tid];
#pragma unroll
                for (int r = 0; r < CLUS; ++r)
                    ((float4*)(peer[r] + OFF_XI))[tid] = v;
            }
        }
        cluster_bar(bar1, tid, ph1); ph1 ^= 1;   // rs + xi visible; Z reusable
    }
}

extern "C" void kernel_launch(void* const* d_in, const int* in_sizes, int n_in,
                              void* d_out, int out_size)
{
    const float* x = (const float*)d_in[0];
    const float* W = (const float*)d_in[1];
    if (n_in >= 2 && in_sizes[0] == 16384 && in_sizes[1] != 16384) {
        const float* t = x; x = W; W = t;
    }
    float* out = (float*)d_out;

    const size_t smem_bytes = (size_t)SMEM_FLOATS * sizeof(float);  // 166432
    cudaFuncSetAttribute(gcn_kernel, cudaFuncAttributeMaxDynamicSharedMemorySize,
                         (int)smem_bytes);
    gcn_kernel<<<32 * CLUS, BLK, smem_bytes>>>(x, W, out);
}